// round 1
// baseline (speedup 1.0000x reference)
#include <cuda_runtime.h>
#include <cuda_bf16.h>

#define EMB 64
#define BN_EPS 1e-5f
#define MAX_L 50000
#define MAX_R 100000

// ---------------- scratch (static device globals; no allocation) -------------
__device__ float g_left_proj[MAX_L * EMB];
__device__ float g_right_proj[MAX_R * EMB];
__device__ float g_S[MAX_R * EMB];       // sum over edges of relu(bn1(joint))
__device__ float g_conv[MAX_R * EMB];
__device__ float g_deg[MAX_R];
__device__ float g_sum1[EMB], g_sumsq1[EMB], g_scale1[EMB], g_shift1[EMB];
__device__ float g_sum2[EMB], g_sumsq2[EMB], g_scale2[EMB], g_shift2[EMB];

// ---------------- zero scratch ----------------------------------------------
__global__ void zero_kernel(int nS, int nDeg) {
    int i = blockIdx.x * blockDim.x + threadIdx.x;
    int stride = gridDim.x * blockDim.x;
    for (int k = i; k < nS; k += stride) g_S[k] = 0.f;
    for (int k = i; k < nDeg; k += stride) g_deg[k] = 0.f;
    if (i < EMB) { g_sum1[i] = 0.f; g_sumsq1[i] = 0.f; g_sum2[i] = 0.f; g_sumsq2[i] = 0.f; }
}

// ---------------- generic [n,64] @ W[64,64]^T + bias*bias_scale --------------
__global__ __launch_bounds__(128) void rowgemm64_kernel(
    const float* __restrict__ X, const float* __restrict__ W,
    const float* __restrict__ bias, const float* __restrict__ bias_scale,
    float* __restrict__ Y, int n)
{
    __shared__ float WT[EMB * EMB];  // WT[k*64+j] = W[j*64+k]
    for (int i = threadIdx.x; i < EMB * EMB; i += blockDim.x) {
        int j = i >> 6, k = i & 63;
        WT[k * EMB + j] = W[i];
    }
    __syncthreads();
    for (int row = blockIdx.x * blockDim.x + threadIdx.x; row < n;
         row += gridDim.x * blockDim.x) {
        float acc[EMB];
        if (bias) {
            float bs = bias_scale ? bias_scale[row] : 1.f;
            #pragma unroll
            for (int j = 0; j < EMB; j++) acc[j] = bias[j] * bs;
        } else {
            #pragma unroll
            for (int j = 0; j < EMB; j++) acc[j] = 0.f;
        }
        const float4* Xr = (const float4*)(X + (size_t)row * EMB);
        #pragma unroll 2
        for (int k4 = 0; k4 < EMB / 4; k4++) {
            float4 xv = Xr[k4];
            const float* wp = &WT[(k4 * 4) * EMB];
            #pragma unroll
            for (int j = 0; j < EMB; j++) acc[j] = fmaf(wp[j], xv.x, acc[j]);
            #pragma unroll
            for (int j = 0; j < EMB; j++) acc[j] = fmaf(wp[EMB + j], xv.y, acc[j]);
            #pragma unroll
            for (int j = 0; j < EMB; j++) acc[j] = fmaf(wp[2 * EMB + j], xv.z, acc[j]);
            #pragma unroll
            for (int j = 0; j < EMB; j++) acc[j] = fmaf(wp[3 * EMB + j], xv.w, acc[j]);
        }
        float4* Yr = (float4*)(Y + (size_t)row * EMB);
        #pragma unroll
        for (int q = 0; q < EMB / 4; q++)
            Yr[q] = make_float4(acc[4 * q], acc[4 * q + 1], acc[4 * q + 2], acc[4 * q + 3]);
    }
}

// ---------------- edge pass 1: BN1 column sums/sumsq -------------------------
__global__ __launch_bounds__(256) void edge_stats_kernel(
    const int* __restrict__ idxL, const int* __restrict__ idxR,
    const float* __restrict__ ef, const float* __restrict__ Wedge, int nE)
{
    int lane = threadIdx.x & 31;
    int gwarp = (blockIdx.x * blockDim.x + threadIdx.x) >> 5;
    int nwarps = (gridDim.x * blockDim.x) >> 5;
    float2 we = ((const float2*)Wedge)[lane];
    float2 s = make_float2(0.f, 0.f), sq = make_float2(0.f, 0.f);
    const float2* LP = (const float2*)g_left_proj;
    const float2* RP = (const float2*)g_right_proj;
    int nchunks = (nE + 31) >> 5;
    for (int ch = gwarp; ch < nchunks; ch += nwarps) {
        int base = ch << 5;
        int e = base + lane;
        int li = 0, ri = 0; float f = 0.f;
        if (e < nE) { li = idxL[e]; ri = idxR[e]; f = ef[e]; }
        int nv = min(32, nE - base);
        for (int j = 0; j < 32; j++) {
            int lj   = __shfl_sync(0xffffffffu, li, j);
            int rj   = __shfl_sync(0xffffffffu, ri, j);
            float fj = __shfl_sync(0xffffffffu, f, j);
            if (j < nv) {
                float2 lp = LP[(size_t)lj * 32 + lane];
                float2 rp = RP[(size_t)rj * 32 + lane];
                float x0 = fmaf(fj, we.x, lp.x + rp.x);
                float x1 = fmaf(fj, we.y, lp.y + rp.y);
                s.x += x0; s.y += x1;
                sq.x = fmaf(x0, x0, sq.x); sq.y = fmaf(x1, x1, sq.y);
            }
        }
    }
    __shared__ float4 red[256];
    red[threadIdx.x] = make_float4(s.x, s.y, sq.x, sq.y);
    __syncthreads();
    for (int off = 128; off >= 32; off >>= 1) {
        if (threadIdx.x < off) {
            float4 a = red[threadIdx.x], b = red[threadIdx.x + off];
            red[threadIdx.x] = make_float4(a.x + b.x, a.y + b.y, a.z + b.z, a.w + b.w);
        }
        __syncthreads();
    }
    if (threadIdx.x < 32) {
        float4 v = red[threadIdx.x];
        atomicAdd(&g_sum1[2 * lane], v.x);
        atomicAdd(&g_sum1[2 * lane + 1], v.y);
        atomicAdd(&g_sumsq1[2 * lane], v.z);
        atomicAdd(&g_sumsq1[2 * lane + 1], v.w);
    }
}

// ---------------- BN finalize ------------------------------------------------
__global__ void bn_fin_kernel(const float* __restrict__ sum, const float* __restrict__ sumsq,
                              const float* __restrict__ gamma, const float* __restrict__ beta,
                              float* __restrict__ scale, float* __restrict__ shift, float invN)
{
    int c = threadIdx.x;
    if (c < EMB) {
        float m = sum[c] * invN;
        float v = sumsq[c] * invN - m * m;
        float sc = gamma[c] * rsqrtf(v + BN_EPS);
        scale[c] = sc;
        shift[c] = beta[c] - m * sc;
    }
}

// ---------------- edge pass 2: recompute joint, bn1+relu, scatter ------------
__global__ __launch_bounds__(256) void edge_scatter_kernel(
    const int* __restrict__ idxL, const int* __restrict__ idxR,
    const float* __restrict__ ef, const float* __restrict__ Wedge, int nE)
{
    int lane = threadIdx.x & 31;
    int hl = lane & 15;
    int half = lane >> 4;
    unsigned hmask = half ? 0xFFFF0000u : 0x0000FFFFu;
    int grp = (blockIdx.x * blockDim.x + threadIdx.x) >> 4;
    int ngrp = (gridDim.x * blockDim.x) >> 4;
    float4 we = ((const float4*)Wedge)[hl];
    float4 sc = ((const float4*)g_scale1)[hl];
    float4 sh = ((const float4*)g_shift1)[hl];
    const float4* LP = (const float4*)g_left_proj;
    const float4* RP = (const float4*)g_right_proj;
    int nchunks = (nE + 15) >> 4;
    for (int ch = grp; ch < nchunks; ch += ngrp) {
        int base = ch << 4;
        int e = base + hl;
        int li = 0, ri = 0; float f = 0.f;
        if (e < nE) { li = idxL[e]; ri = idxR[e]; f = ef[e]; }
        int nv = min(16, nE - base);
        for (int j = 0; j < 16; j++) {
            int lj   = __shfl_sync(hmask, li, j, 16);
            int rj   = __shfl_sync(hmask, ri, j, 16);
            float fj = __shfl_sync(hmask, f, j, 16);
            if (j < nv) {
                float4 lp = LP[(size_t)lj * 16 + hl];
                float4 rp = RP[(size_t)rj * 16 + hl];
                float4 y;
                float x;
                x = fmaf(fj, we.x, lp.x + rp.x); y.x = fmaxf(fmaf(x, sc.x, sh.x), 0.f);
                x = fmaf(fj, we.y, lp.y + rp.y); y.y = fmaxf(fmaf(x, sc.y, sh.y), 0.f);
                x = fmaf(fj, we.z, lp.z + rp.z); y.z = fmaxf(fmaf(x, sc.z, sh.z), 0.f);
                x = fmaf(fj, we.w, lp.w + rp.w); y.w = fmaxf(fmaf(x, sc.w, sh.w), 0.f);
                atomicAdd(((float4*)(g_S + (size_t)rj * EMB)) + hl, y);
                if (hl == 0) atomicAdd(&g_deg[rj], 1.0f);
            }
        }
    }
}

// ---------------- column stats over a dense [n,64] matrix --------------------
__global__ __launch_bounds__(256) void col_stats_kernel(
    const float* __restrict__ X, int n, float* __restrict__ sum, float* __restrict__ sumsq)
{
    int lane = threadIdx.x & 31;
    int gwarp = (blockIdx.x * blockDim.x + threadIdx.x) >> 5;
    int nwarps = (gridDim.x * blockDim.x) >> 5;
    float2 s = make_float2(0.f, 0.f), sq = make_float2(0.f, 0.f);
    const float2* X2 = (const float2*)X;
    for (int r = gwarp; r < n; r += nwarps) {
        float2 v = X2[(size_t)r * 32 + lane];
        s.x += v.x; s.y += v.y;
        sq.x = fmaf(v.x, v.x, sq.x); sq.y = fmaf(v.y, v.y, sq.y);
    }
    __shared__ float4 red[256];
    red[threadIdx.x] = make_float4(s.x, s.y, sq.x, sq.y);
    __syncthreads();
    for (int off = 128; off >= 32; off >>= 1) {
        if (threadIdx.x < off) {
            float4 a = red[threadIdx.x], b = red[threadIdx.x + off];
            red[threadIdx.x] = make_float4(a.x + b.x, a.y + b.y, a.z + b.z, a.w + b.w);
        }
        __syncthreads();
    }
    if (threadIdx.x < 32) {
        float4 v = red[threadIdx.x];
        atomicAdd(&sum[2 * lane], v.x);
        atomicAdd(&sum[2 * lane + 1], v.y);
        atomicAdd(&sumsq[2 * lane], v.z);
        atomicAdd(&sumsq[2 * lane + 1], v.w);
    }
}

// ---------------- final: bn2 + concat + 2-layer MLP --------------------------
__global__ __launch_bounds__(128) void final_kernel(
    const float* __restrict__ right,
    const float* __restrict__ W1, const float* __restrict__ b1,
    const float* __restrict__ W2, const float* __restrict__ b2,
    float* __restrict__ out, int nR)
{
    __shared__ float Wsh[2 * EMB * EMB];   // phase1: W1T[c*64+j]; phase2: W2T reuses
    __shared__ float sb[EMB], ssc[EMB], ssh[EMB];
    for (int i = threadIdx.x; i < 2 * EMB * EMB; i += blockDim.x) {
        int j = i >> 7, c = i & 127;       // W1 is [64,128]
        Wsh[c * EMB + j] = W1[i];
    }
    if (threadIdx.x < EMB) {
        sb[threadIdx.x] = b1[threadIdx.x];
        ssc[threadIdx.x] = g_scale2[threadIdx.x];
        ssh[threadIdx.x] = g_shift2[threadIdx.x];
    }
    __syncthreads();

    int row = blockIdx.x * blockDim.x + threadIdx.x;
    float h[EMB];
    if (row < nR) {
        #pragma unroll
        for (int j = 0; j < EMB; j++) h[j] = sb[j];
        const float4* cv = (const float4*)(g_conv + (size_t)row * EMB);
        #pragma unroll 2
        for (int k4 = 0; k4 < 16; k4++) {
            float4 v = cv[k4];
            int c = k4 * 4;
            float x0 = fmaf(v.x, ssc[c], ssh[c]);
            float x1 = fmaf(v.y, ssc[c + 1], ssh[c + 1]);
            float x2 = fmaf(v.z, ssc[c + 2], ssh[c + 2]);
            float x3 = fmaf(v.w, ssc[c + 3], ssh[c + 3]);
            const float* wp = &Wsh[c * EMB];
            #pragma unroll
            for (int j = 0; j < EMB; j++) h[j] = fmaf(wp[j], x0, h[j]);
            #pragma unroll
            for (int j = 0; j < EMB; j++) h[j] = fmaf(wp[EMB + j], x1, h[j]);
            #pragma unroll
            for (int j = 0; j < EMB; j++) h[j] = fmaf(wp[2 * EMB + j], x2, h[j]);
            #pragma unroll
            for (int j = 0; j < EMB; j++) h[j] = fmaf(wp[3 * EMB + j], x3, h[j]);
        }
        const float4* rf = (const float4*)(right + (size_t)row * EMB);
        #pragma unroll 2
        for (int k4 = 0; k4 < 16; k4++) {
            float4 v = rf[k4];
            int c = 64 + k4 * 4;
            const float* wp = &Wsh[c * EMB];
            #pragma unroll
            for (int j = 0; j < EMB; j++) h[j] = fmaf(wp[j], v.x, h[j]);
            #pragma unroll
            for (int j = 0; j < EMB; j++) h[j] = fmaf(wp[EMB + j], v.y, h[j]);
            #pragma unroll
            for (int j = 0; j < EMB; j++) h[j] = fmaf(wp[2 * EMB + j], v.z, h[j]);
            #pragma unroll
            for (int j = 0; j < EMB; j++) h[j] = fmaf(wp[3 * EMB + j], v.w, h[j]);
        }
        #pragma unroll
        for (int j = 0; j < EMB; j++) h[j] = fmaxf(h[j], 0.f);
    }
    __syncthreads();
    // phase 2: load W2T and b2
    for (int i = threadIdx.x; i < EMB * EMB; i += blockDim.x) {
        int j = i >> 6, c = i & 63;
        Wsh[c * EMB + j] = W2[i];
    }
    if (threadIdx.x < EMB) sb[threadIdx.x] = b2[threadIdx.x];
    __syncthreads();
    if (row < nR) {
        float* orow = out + (size_t)row * EMB;
        #pragma unroll
        for (int jb = 0; jb < 4; jb++) {
            float acc[16];
            #pragma unroll
            for (int j = 0; j < 16; j++) acc[j] = sb[jb * 16 + j];
            #pragma unroll 4
            for (int c = 0; c < EMB; c++) {
                float hc = h[c];
                const float* wp = &Wsh[c * EMB + jb * 16];
                #pragma unroll
                for (int j = 0; j < 16; j++) acc[j] = fmaf(wp[j], hc, acc[j]);
            }
            float4* o4 = (float4*)(orow + jb * 16);
            #pragma unroll
            for (int q = 0; q < 4; q++)
                o4[q] = make_float4(fmaxf(acc[4 * q], 0.f), fmaxf(acc[4 * q + 1], 0.f),
                                    fmaxf(acc[4 * q + 2], 0.f), fmaxf(acc[4 * q + 3], 0.f));
        }
    }
}

// ---------------- launch -----------------------------------------------------
extern "C" void kernel_launch(void* const* d_in, const int* in_sizes, int n_in,
                              void* d_out, int out_size)
{
    const float* left  = (const float*)d_in[0];
    const int*   eidx  = (const int*)d_in[1];
    const float* ef    = (const float*)d_in[2];
    const float* right = (const float*)d_in[3];
    int off = (n_in >= 19) ? 1 : 0;   // skip output_size scalar input if present
    const float* W_left    = (const float*)d_in[4 + off];
    const float* b_left    = (const float*)d_in[5 + off];
    const float* W_edge    = (const float*)d_in[6 + off];
    const float* W_right   = (const float*)d_in[7 + off];
    const float* bn1_gamma = (const float*)d_in[8 + off];
    const float* bn1_beta  = (const float*)d_in[9 + off];
    const float* W_final   = (const float*)d_in[10 + off];
    const float* b_final   = (const float*)d_in[11 + off];
    const float* bn2_gamma = (const float*)d_in[12 + off];
    const float* bn2_beta  = (const float*)d_in[13 + off];
    const float* W_out1    = (const float*)d_in[14 + off];
    const float* b_out1    = (const float*)d_in[15 + off];
    const float* W_out2    = (const float*)d_in[16 + off];
    const float* b_out2    = (const float*)d_in[17 + off];
    float* out = (float*)d_out;

    int nL = in_sizes[0] / EMB;
    int nE = in_sizes[2];
    int nR = in_sizes[3] / EMB;

    // device-global scratch pointers (resolved at compile time via symbols)
    float* lp; cudaGetSymbolAddress((void**)&lp, g_left_proj);
    float* rp; cudaGetSymbolAddress((void**)&rp, g_right_proj);
    float* Sp; cudaGetSymbolAddress((void**)&Sp, g_S);
    float* cp; cudaGetSymbolAddress((void**)&cp, g_conv);
    float* dg; cudaGetSymbolAddress((void**)&dg, g_deg);
    float* s1; cudaGetSymbolAddress((void**)&s1, g_sum1);
    float* q1; cudaGetSymbolAddress((void**)&q1, g_sumsq1);
    float* sc1; cudaGetSymbolAddress((void**)&sc1, g_scale1);
    float* sh1; cudaGetSymbolAddress((void**)&sh1, g_shift1);
    float* s2; cudaGetSymbolAddress((void**)&s2, g_sum2);
    float* q2; cudaGetSymbolAddress((void**)&q2, g_sumsq2);
    float* sc2; cudaGetSymbolAddress((void**)&sc2, g_scale2);
    float* sh2; cudaGetSymbolAddress((void**)&sh2, g_shift2);

    // 1) zero scratch
    zero_kernel<<<1024, 256>>>(nR * EMB, nR);
    // 2) projections
    rowgemm64_kernel<<<(nL + 127) / 128, 128>>>(left, W_left, b_left, nullptr, lp, nL);
    rowgemm64_kernel<<<(nR + 127) / 128, 128>>>(right, W_right, nullptr, nullptr, rp, nR);
    // 3) BN1 stats over edges
    edge_stats_kernel<<<592, 256>>>(eidx, eidx + nE, ef, W_edge, nE);
    bn_fin_kernel<<<1, EMB>>>(s1, q1, bn1_gamma, bn1_beta, sc1, sh1, 1.0f / (float)nE);
    // 4) scatter relu(bn1(joint)) into S + degrees
    edge_scatter_kernel<<<1184, 256>>>(eidx, eidx + nE, ef, W_edge, nE);
    // 5) conv = S @ W_final^T + deg * b_final
    rowgemm64_kernel<<<(nR + 127) / 128, 128>>>(Sp, W_final, b_final, dg, cp, nR);
    // 6) BN2 stats + finalize
    col_stats_kernel<<<296, 256>>>(cp, nR, s2, q2);
    bn_fin_kernel<<<1, EMB>>>(s2, q2, bn2_gamma, bn2_beta, sc2, sh2, 1.0f / (float)nR);
    // 7) final MLP
    final_kernel<<<(nR + 127) / 128, 128>>>(right, W_out1, b_out1, W_out2, b_out2, out, nR);
}

// round 2
// speedup vs baseline: 1.0079x; 1.0079x over previous
#include <cuda_runtime.h>
#include <cuda_bf16.h>

#define EMB 64
#define BN_EPS 1e-5f
#define MAX_L 50000
#define MAX_R 100000

// ---------------- scratch (static device globals; no allocation) -------------
__device__ float g_left_proj[MAX_L * EMB];
__device__ float g_right_proj[MAX_R * EMB];
__device__ float g_S[MAX_R * EMB];       // sum over edges of relu(bn1(joint))
__device__ float g_conv[MAX_R * EMB];
__device__ float g_deg[MAX_R];
__device__ float g_sum1[EMB], g_sumsq1[EMB], g_scale1[EMB], g_shift1[EMB];
__device__ float g_sum2[EMB], g_sumsq2[EMB], g_scale2[EMB], g_shift2[EMB];

// ---------------- zero scratch ----------------------------------------------
__global__ void zero_kernel(int nS, int nDeg) {
    int i = blockIdx.x * blockDim.x + threadIdx.x;
    int stride = gridDim.x * blockDim.x;
    for (int k = i; k < nS; k += stride) g_S[k] = 0.f;
    for (int k = i; k < nDeg; k += stride) g_deg[k] = 0.f;
    if (i < EMB) { g_sum1[i] = 0.f; g_sumsq1[i] = 0.f; g_sum2[i] = 0.f; g_sumsq2[i] = 0.f; }
}

// ---------------- fused projections: left and right in one launch ------------
__global__ __launch_bounds__(128) void proj_kernel(
    const float* __restrict__ XL, const float* __restrict__ WL, const float* __restrict__ bL,
    const float* __restrict__ XR, const float* __restrict__ WR,
    int nL, int nR, int nbL)
{
    bool isL = (int)blockIdx.x < nbL;
    const float* X = isL ? XL : XR;
    const float* W = isL ? WL : WR;
    float* Y = isL ? g_left_proj : g_right_proj;
    int n = isL ? nL : nR;
    int bid = isL ? blockIdx.x : blockIdx.x - nbL;

    __shared__ float WT[EMB * EMB];  // WT[k*64+j] = W[j*64+k]
    __shared__ float bsh[EMB];
    for (int i = threadIdx.x; i < EMB * EMB; i += blockDim.x) {
        int j = i >> 6, k = i & 63;
        WT[k * EMB + j] = W[i];
    }
    if (threadIdx.x < EMB) bsh[threadIdx.x] = isL ? bL[threadIdx.x] : 0.f;
    __syncthreads();

    int row = bid * blockDim.x + threadIdx.x;
    if (row >= n) return;
    float acc[EMB];
    #pragma unroll
    for (int j = 0; j < EMB; j++) acc[j] = bsh[j];
    const float4* Xr = (const float4*)(X + (size_t)row * EMB);
    #pragma unroll 2
    for (int k4 = 0; k4 < EMB / 4; k4++) {
        float4 xv = Xr[k4];
        const float* wp = &WT[(k4 * 4) * EMB];
        #pragma unroll
        for (int j = 0; j < EMB; j++) acc[j] = fmaf(wp[j], xv.x, acc[j]);
        #pragma unroll
        for (int j = 0; j < EMB; j++) acc[j] = fmaf(wp[EMB + j], xv.y, acc[j]);
        #pragma unroll
        for (int j = 0; j < EMB; j++) acc[j] = fmaf(wp[2 * EMB + j], xv.z, acc[j]);
        #pragma unroll
        for (int j = 0; j < EMB; j++) acc[j] = fmaf(wp[3 * EMB + j], xv.w, acc[j]);
    }
    float4* Yr = (float4*)(Y + (size_t)row * EMB);
    #pragma unroll
    for (int q = 0; q < EMB / 4; q++)
        Yr[q] = make_float4(acc[4 * q], acc[4 * q + 1], acc[4 * q + 2], acc[4 * q + 3]);
}

// ---------------- edge pass 1: BN1 column sums/sumsq (16-lane float4) --------
__global__ __launch_bounds__(256) void edge_stats_kernel(
    const int* __restrict__ idxL, const int* __restrict__ idxR,
    const float* __restrict__ ef, const float* __restrict__ Wedge, int nE)
{
    int lane = threadIdx.x & 31;
    int hl = lane & 15;
    unsigned hmask = (lane & 16) ? 0xFFFF0000u : 0x0000FFFFu;
    int grp = (blockIdx.x * blockDim.x + threadIdx.x) >> 4;
    int ngrp = (gridDim.x * blockDim.x) >> 4;
    float4 we = ((const float4*)Wedge)[hl];
    float4 s = make_float4(0.f, 0.f, 0.f, 0.f);
    float4 sq = make_float4(0.f, 0.f, 0.f, 0.f);
    const float4* LP = (const float4*)g_left_proj;
    const float4* RP = (const float4*)g_right_proj;

    int nfull = nE >> 4;   // full 16-edge chunks
    for (int ch = grp; ch < nfull; ch += ngrp) {
        int e = (ch << 4) + hl;
        int li = idxL[e], ri = idxR[e];
        float f = ef[e];
        #pragma unroll
        for (int j = 0; j < 16; j++) {
            int lj   = __shfl_sync(hmask, li, j, 16);
            int rj   = __shfl_sync(hmask, ri, j, 16);
            float fj = __shfl_sync(hmask, f, j, 16);
            float4 lp = LP[(size_t)lj * 16 + hl];
            float4 rp = RP[(size_t)rj * 16 + hl];
            float x;
            x = fmaf(fj, we.x, lp.x + rp.x); s.x += x; sq.x = fmaf(x, x, sq.x);
            x = fmaf(fj, we.y, lp.y + rp.y); s.y += x; sq.y = fmaf(x, x, sq.y);
            x = fmaf(fj, we.z, lp.z + rp.z); s.z += x; sq.z = fmaf(x, x, sq.z);
            x = fmaf(fj, we.w, lp.w + rp.w); s.w += x; sq.w = fmaf(x, x, sq.w);
        }
    }
    // tail (edges beyond last full chunk): handled by group 0 only
    if (grp == 0) {
        for (int e = nfull << 4; e < nE; e++) {
            int lj = idxL[e], rj = idxR[e];
            float fj = ef[e];
            float4 lp = LP[(size_t)lj * 16 + hl];
            float4 rp = RP[(size_t)rj * 16 + hl];
            float x;
            x = fmaf(fj, we.x, lp.x + rp.x); s.x += x; sq.x = fmaf(x, x, sq.x);
            x = fmaf(fj, we.y, lp.y + rp.y); s.y += x; sq.y = fmaf(x, x, sq.y);
            x = fmaf(fj, we.z, lp.z + rp.z); s.z += x; sq.z = fmaf(x, x, sq.z);
            x = fmaf(fj, we.w, lp.w + rp.w); s.w += x; sq.w = fmaf(x, x, sq.w);
        }
    }
    // combine the two 16-lane halves of each warp (same columns)
    s.x += __shfl_xor_sync(0xffffffffu, s.x, 16);
    s.y += __shfl_xor_sync(0xffffffffu, s.y, 16);
    s.z += __shfl_xor_sync(0xffffffffu, s.z, 16);
    s.w += __shfl_xor_sync(0xffffffffu, s.w, 16);
    sq.x += __shfl_xor_sync(0xffffffffu, sq.x, 16);
    sq.y += __shfl_xor_sync(0xffffffffu, sq.y, 16);
    sq.z += __shfl_xor_sync(0xffffffffu, sq.z, 16);
    sq.w += __shfl_xor_sync(0xffffffffu, sq.w, 16);

    __shared__ float cs[EMB], cq[EMB];
    if (threadIdx.x < EMB) { cs[threadIdx.x] = 0.f; cq[threadIdx.x] = 0.f; }
    __syncthreads();
    if (lane < 16) {
        atomicAdd(&cs[4 * hl + 0], s.x);
        atomicAdd(&cs[4 * hl + 1], s.y);
        atomicAdd(&cs[4 * hl + 2], s.z);
        atomicAdd(&cs[4 * hl + 3], s.w);
        atomicAdd(&cq[4 * hl + 0], sq.x);
        atomicAdd(&cq[4 * hl + 1], sq.y);
        atomicAdd(&cq[4 * hl + 2], sq.z);
        atomicAdd(&cq[4 * hl + 3], sq.w);
    }
    __syncthreads();
    if (threadIdx.x < EMB) {
        atomicAdd(&g_sum1[threadIdx.x], cs[threadIdx.x]);
        atomicAdd(&g_sumsq1[threadIdx.x], cq[threadIdx.x]);
    }
}

// ---------------- BN finalize ------------------------------------------------
__global__ void bn_fin_kernel(const float* __restrict__ sum, const float* __restrict__ sumsq,
                              const float* __restrict__ gamma, const float* __restrict__ beta,
                              float* __restrict__ scale, float* __restrict__ shift, float invN)
{
    int c = threadIdx.x;
    if (c < EMB) {
        float m = sum[c] * invN;
        float v = sumsq[c] * invN - m * m;
        float sc = gamma[c] * rsqrtf(v + BN_EPS);
        scale[c] = sc;
        shift[c] = beta[c] - m * sc;
    }
}

// ---------------- edge pass 2: recompute joint, bn1+relu, scatter ------------
__global__ __launch_bounds__(256) void edge_scatter_kernel(
    const int* __restrict__ idxL, const int* __restrict__ idxR,
    const float* __restrict__ ef, const float* __restrict__ Wedge, int nE)
{
    int lane = threadIdx.x & 31;
    int hl = lane & 15;
    unsigned hmask = (lane & 16) ? 0xFFFF0000u : 0x0000FFFFu;
    int grp = (blockIdx.x * blockDim.x + threadIdx.x) >> 4;
    int ngrp = (gridDim.x * blockDim.x) >> 4;
    float4 we = ((const float4*)Wedge)[hl];
    float4 sc = ((const float4*)g_scale1)[hl];
    float4 sh = ((const float4*)g_shift1)[hl];
    const float4* LP = (const float4*)g_left_proj;
    const float4* RP = (const float4*)g_right_proj;

    int nfull = nE >> 4;
    for (int ch = grp; ch < nfull; ch += ngrp) {
        int e = (ch << 4) + hl;
        int li = idxL[e], ri = idxR[e];
        float f = ef[e];
        #pragma unroll
        for (int j = 0; j < 16; j++) {
            int lj   = __shfl_sync(hmask, li, j, 16);
            int rj   = __shfl_sync(hmask, ri, j, 16);
            float fj = __shfl_sync(hmask, f, j, 16);
            float4 lp = LP[(size_t)lj * 16 + hl];
            float4 rp = RP[(size_t)rj * 16 + hl];
            float4 y;
            float x;
            x = fmaf(fj, we.x, lp.x + rp.x); y.x = fmaxf(fmaf(x, sc.x, sh.x), 0.f);
            x = fmaf(fj, we.y, lp.y + rp.y); y.y = fmaxf(fmaf(x, sc.y, sh.y), 0.f);
            x = fmaf(fj, we.z, lp.z + rp.z); y.z = fmaxf(fmaf(x, sc.z, sh.z), 0.f);
            x = fmaf(fj, we.w, lp.w + rp.w); y.w = fmaxf(fmaf(x, sc.w, sh.w), 0.f);
            atomicAdd(((float4*)(g_S + (size_t)rj * EMB)) + hl, y);
            if (hl == 0) atomicAdd(&g_deg[rj], 1.0f);
        }
    }
    if (grp == 0) {
        for (int e = nfull << 4; e < nE; e++) {
            int lj = idxL[e], rj = idxR[e];
            float fj = ef[e];
            float4 lp = LP[(size_t)lj * 16 + hl];
            float4 rp = RP[(size_t)rj * 16 + hl];
            float4 y;
            float x;
            x = fmaf(fj, we.x, lp.x + rp.x); y.x = fmaxf(fmaf(x, sc.x, sh.x), 0.f);
            x = fmaf(fj, we.y, lp.y + rp.y); y.y = fmaxf(fmaf(x, sc.y, sh.y), 0.f);
            x = fmaf(fj, we.z, lp.z + rp.z); y.z = fmaxf(fmaf(x, sc.z, sh.z), 0.f);
            x = fmaf(fj, we.w, lp.w + rp.w); y.w = fmaxf(fmaf(x, sc.w, sh.w), 0.f);
            atomicAdd(((float4*)(g_S + (size_t)rj * EMB)) + hl, y);
            if (hl == 0) atomicAdd(&g_deg[rj], 1.0f);
        }
    }
}

// ---------------- conv = S @ Wf^T + deg*b, fused BN2 column stats ------------
__global__ __launch_bounds__(128) void conv_stats_kernel(
    const float* __restrict__ X, const float* __restrict__ W,
    const float* __restrict__ bias, const float* __restrict__ deg,
    float* __restrict__ Y, int n, int T)
{
    __shared__ float WT[EMB * EMB];
    __shared__ float bsh[EMB];
    __shared__ float cs[EMB], cq[EMB];
    for (int i = threadIdx.x; i < EMB * EMB; i += blockDim.x) {
        int j = i >> 6, k = i & 63;
        WT[k * EMB + j] = W[i];
    }
    if (threadIdx.x < EMB) {
        bsh[threadIdx.x] = bias[threadIdx.x];
        cs[threadIdx.x] = 0.f;
        cq[threadIdx.x] = 0.f;
    }
    __syncthreads();

    int gtid = blockIdx.x * blockDim.x + threadIdx.x;
    int lane = threadIdx.x & 31;
    int iters = (n + T - 1) / T;
    for (int it = 0; it < iters; it++) {
        int row = it * T + gtid;
        bool valid = row < n;
        float acc[EMB];
        if (valid) {
            float bs = deg[row];
            #pragma unroll
            for (int j = 0; j < EMB; j++) acc[j] = bsh[j] * bs;
            const float4* Xr = (const float4*)(X + (size_t)row * EMB);
            #pragma unroll 2
            for (int k4 = 0; k4 < EMB / 4; k4++) {
                float4 xv = Xr[k4];
                const float* wp = &WT[(k4 * 4) * EMB];
                #pragma unroll
                for (int j = 0; j < EMB; j++) acc[j] = fmaf(wp[j], xv.x, acc[j]);
                #pragma unroll
                for (int j = 0; j < EMB; j++) acc[j] = fmaf(wp[EMB + j], xv.y, acc[j]);
                #pragma unroll
                for (int j = 0; j < EMB; j++) acc[j] = fmaf(wp[2 * EMB + j], xv.z, acc[j]);
                #pragma unroll
                for (int j = 0; j < EMB; j++) acc[j] = fmaf(wp[3 * EMB + j], xv.w, acc[j]);
            }
            float4* Yr = (float4*)(Y + (size_t)row * EMB);
            #pragma unroll
            for (int q = 0; q < EMB / 4; q++)
                Yr[q] = make_float4(acc[4 * q], acc[4 * q + 1], acc[4 * q + 2], acc[4 * q + 3]);
        } else {
            #pragma unroll
            for (int j = 0; j < EMB; j++) acc[j] = 0.f;
        }
        // per-warp column reduction into shared stats
        #pragma unroll
        for (int j = 0; j < EMB; j++) {
            float v = acc[j];
            float v2 = v * v;
            #pragma unroll
            for (int off = 16; off; off >>= 1) {
                v  += __shfl_xor_sync(0xffffffffu, v, off);
                v2 += __shfl_xor_sync(0xffffffffu, v2, off);
            }
            if (lane == 0) { atomicAdd(&cs[j], v); atomicAdd(&cq[j], v2); }
        }
    }
    __syncthreads();
    if (threadIdx.x < EMB) {
        atomicAdd(&g_sum2[threadIdx.x], cs[threadIdx.x]);
        atomicAdd(&g_sumsq2[threadIdx.x], cq[threadIdx.x]);
    }
}

// ---------------- final: bn2 + concat + 2-layer MLP --------------------------
__global__ __launch_bounds__(128) void final_kernel(
    const float* __restrict__ right,
    const float* __restrict__ W1, const float* __restrict__ b1,
    const float* __restrict__ W2, const float* __restrict__ b2,
    float* __restrict__ out, int nR)
{
    __shared__ float Wsh[2 * EMB * EMB];   // phase1: W1T[c*64+j]; phase2: W2T reuses
    __shared__ float sb[EMB], ssc[EMB], ssh[EMB];
    for (int i = threadIdx.x; i < 2 * EMB * EMB; i += blockDim.x) {
        int j = i >> 7, c = i & 127;       // W1 is [64,128]
        Wsh[c * EMB + j] = W1[i];
    }
    if (threadIdx.x < EMB) {
        sb[threadIdx.x] = b1[threadIdx.x];
        ssc[threadIdx.x] = g_scale2[threadIdx.x];
        ssh[threadIdx.x] = g_shift2[threadIdx.x];
    }
    __syncthreads();

    int row = blockIdx.x * blockDim.x + threadIdx.x;
    float h[EMB];
    if (row < nR) {
        #pragma unroll
        for (int j = 0; j < EMB; j++) h[j] = sb[j];
        const float4* cv = (const float4*)(g_conv + (size_t)row * EMB);
        #pragma unroll 2
        for (int k4 = 0; k4 < 16; k4++) {
            float4 v = cv[k4];
            int c = k4 * 4;
            float x0 = fmaf(v.x, ssc[c], ssh[c]);
            float x1 = fmaf(v.y, ssc[c + 1], ssh[c + 1]);
            float x2 = fmaf(v.z, ssc[c + 2], ssh[c + 2]);
            float x3 = fmaf(v.w, ssc[c + 3], ssh[c + 3]);
            const float* wp = &Wsh[c * EMB];
            #pragma unroll
            for (int j = 0; j < EMB; j++) h[j] = fmaf(wp[j], x0, h[j]);
            #pragma unroll
            for (int j = 0; j < EMB; j++) h[j] = fmaf(wp[EMB + j], x1, h[j]);
            #pragma unroll
            for (int j = 0; j < EMB; j++) h[j] = fmaf(wp[2 * EMB + j], x2, h[j]);
            #pragma unroll
            for (int j = 0; j < EMB; j++) h[j] = fmaf(wp[3 * EMB + j], x3, h[j]);
        }
        const float4* rf = (const float4*)(right + (size_t)row * EMB);
        #pragma unroll 2
        for (int k4 = 0; k4 < 16; k4++) {
            float4 v = rf[k4];
            int c = 64 + k4 * 4;
            const float* wp = &Wsh[c * EMB];
            #pragma unroll
            for (int j = 0; j < EMB; j++) h[j] = fmaf(wp[j], v.x, h[j]);
            #pragma unroll
            for (int j = 0; j < EMB; j++) h[j] = fmaf(wp[EMB + j], v.y, h[j]);
            #pragma unroll
            for (int j = 0; j < EMB; j++) h[j] = fmaf(wp[2 * EMB + j], v.z, h[j]);
            #pragma unroll
            for (int j = 0; j < EMB; j++) h[j] = fmaf(wp[3 * EMB + j], v.w, h[j]);
        }
        #pragma unroll
        for (int j = 0; j < EMB; j++) h[j] = fmaxf(h[j], 0.f);
    }
    __syncthreads();
    // phase 2: load W2T and b2
    for (int i = threadIdx.x; i < EMB * EMB; i += blockDim.x) {
        int j = i >> 6, c = i & 63;
        Wsh[c * EMB + j] = W2[i];
    }
    if (threadIdx.x < EMB) sb[threadIdx.x] = b2[threadIdx.x];
    __syncthreads();
    if (row < nR) {
        float* orow = out + (size_t)row * EMB;
        #pragma unroll
        for (int jb = 0; jb < 4; jb++) {
            float acc[16];
            #pragma unroll
            for (int j = 0; j < 16; j++) acc[j] = sb[jb * 16 + j];
            #pragma unroll 4
            for (int c = 0; c < EMB; c++) {
                float hc = h[c];
                const float* wp = &Wsh[c * EMB + jb * 16];
                #pragma unroll
                for (int j = 0; j < 16; j++) acc[j] = fmaf(wp[j], hc, acc[j]);
            }
            float4* o4 = (float4*)(orow + jb * 16);
            #pragma unroll
            for (int q = 0; q < 4; q++)
                o4[q] = make_float4(fmaxf(acc[4 * q], 0.f), fmaxf(acc[4 * q + 1], 0.f),
                                    fmaxf(acc[4 * q + 2], 0.f), fmaxf(acc[4 * q + 3], 0.f));
        }
    }
}

// ---------------- launch -----------------------------------------------------
extern "C" void kernel_launch(void* const* d_in, const int* in_sizes, int n_in,
                              void* d_out, int out_size)
{
    const float* left  = (const float*)d_in[0];
    const int*   eidx  = (const int*)d_in[1];
    const float* ef    = (const float*)d_in[2];
    const float* right = (const float*)d_in[3];
    int off = (n_in >= 19) ? 1 : 0;   // skip output_size scalar input if present
    const float* W_left    = (const float*)d_in[4 + off];
    const float* b_left    = (const float*)d_in[5 + off];
    const float* W_edge    = (const float*)d_in[6 + off];
    const float* W_right   = (const float*)d_in[7 + off];
    const float* bn1_gamma = (const float*)d_in[8 + off];
    const float* bn1_beta  = (const float*)d_in[9 + off];
    const float* W_final   = (const float*)d_in[10 + off];
    const float* b_final   = (const float*)d_in[11 + off];
    const float* bn2_gamma = (const float*)d_in[12 + off];
    const float* bn2_beta  = (const float*)d_in[13 + off];
    const float* W_out1    = (const float*)d_in[14 + off];
    const float* b_out1    = (const float*)d_in[15 + off];
    const float* W_out2    = (const float*)d_in[16 + off];
    const float* b_out2    = (const float*)d_in[17 + off];
    float* out = (float*)d_out;

    int nL = in_sizes[0] / EMB;
    int nE = in_sizes[2];
    int nR = in_sizes[3] / EMB;

    float* Sp; cudaGetSymbolAddress((void**)&Sp, g_S);
    float* cp; cudaGetSymbolAddress((void**)&cp, g_conv);
    float* dg; cudaGetSymbolAddress((void**)&dg, g_deg);
    float* s1; cudaGetSymbolAddress((void**)&s1, g_sum1);
    float* q1; cudaGetSymbolAddress((void**)&q1, g_sumsq1);
    float* sc1; cudaGetSymbolAddress((void**)&sc1, g_scale1);
    float* sh1; cudaGetSymbolAddress((void**)&sh1, g_shift1);
    float* s2; cudaGetSymbolAddress((void**)&s2, g_sum2);
    float* q2; cudaGetSymbolAddress((void**)&q2, g_sumsq2);
    float* sc2; cudaGetSymbolAddress((void**)&sc2, g_scale2);
    float* sh2; cudaGetSymbolAddress((void**)&sh2, g_shift2);

    int nbL = (nL + 127) / 128;
    int nbR = (nR + 127) / 128;

    // 1) zero scratch
    zero_kernel<<<1024, 256>>>(nR * EMB, nR);
    // 2) both projections in one launch
    proj_kernel<<<nbL + nbR, 128>>>(left, W_left, b_left, right, W_right, nL, nR, nbL);
    // 3) BN1 stats over edges (full occupancy: 8 blocks x 256 / SM)
    edge_stats_kernel<<<1184, 256>>>(eidx, eidx + nE, ef, W_edge, nE);
    bn_fin_kernel<<<1, EMB>>>(s1, q1, bn1_gamma, bn1_beta, sc1, sh1, 1.0f / (float)nE);
    // 4) scatter relu(bn1(joint)) into S + degrees
    edge_scatter_kernel<<<1184, 256>>>(eidx, eidx + nE, ef, W_edge, nE);
    // 5) conv = S @ W_final^T + deg * b_final, with fused BN2 stats
    conv_stats_kernel<<<nbR, 128>>>(Sp, W_final, b_final, dg, cp, nR, nbR * 128);
    bn_fin_kernel<<<1, EMB>>>(s2, q2, bn2_gamma, bn2_beta, sc2, sh2, 1.0f / (float)nR);
    // 6) final MLP
    final_kernel<<<nbR, 128>>>(right, W_out1, b_out1, W_out2, b_out2, out, nR);
}

// round 4
// speedup vs baseline: 1.0222x; 1.0142x over previous
#include <cuda_runtime.h>
#include <cuda_bf16.h>

#define EMB 64
#define BN_EPS 1e-5f
#define MAX_L 50000
#define MAX_R 100000
#define MAX_E 1100000

// ---------------- scratch (static device globals; no allocation) -------------
__device__ float g_left_proj[MAX_L * EMB];
__device__ float g_right_proj[MAX_R * EMB];
__device__ float g_S[MAX_R * EMB];       // per-right-node sum of relu(bn1(joint))
__device__ float g_conv[MAX_R * EMB];
__device__ int   g_cnt[MAX_R];           // degree of each right node
__device__ int   g_off[MAX_R];           // segment start
__device__ int   g_cur[MAX_R];           // binning cursor
__device__ int   g_total;
__device__ int2  g_sorted[MAX_E];        // {left_idx, f_bits} grouped by right node
__device__ float g_sum1[EMB], g_sumsq1[EMB], g_scale1[EMB], g_shift1[EMB];
__device__ float g_sum2[EMB], g_sumsq2[EMB], g_scale2[EMB], g_shift2[EMB];

// ---------------- zero scratch ----------------------------------------------
__global__ void zero_kernel(int nR) {
    int i = blockIdx.x * blockDim.x + threadIdx.x;
    int stride = gridDim.x * blockDim.x;
    for (int k = i; k < nR; k += stride) g_cnt[k] = 0;
    if (i < EMB) { g_sum1[i] = 0.f; g_sumsq1[i] = 0.f; g_sum2[i] = 0.f; g_sumsq2[i] = 0.f; }
    if (i == 0) g_total = 0;
}

// ---------------- count: histogram of right indices --------------------------
__global__ __launch_bounds__(256) void count_kernel(const int* __restrict__ idxR, int nE) {
    int i = blockIdx.x * blockDim.x + threadIdx.x;
    int stride = gridDim.x * blockDim.x;
    for (int e = i; e < nE; e += stride) atomicAdd(&g_cnt[idxR[e]], 1);
}

// ---------------- assign: contiguous segment offsets (order-free) ------------
__global__ __launch_bounds__(256) void assign_kernel(int nR) {
    int gtid = blockIdx.x * blockDim.x + threadIdx.x;
    int lane = threadIdx.x & 31;
    int stride = gridDim.x * blockDim.x;
    int niter = (nR + stride - 1) / stride;
    for (int it = 0; it < niter; it++) {
        int i = it * stride + gtid;
        int c = (i < nR) ? g_cnt[i] : 0;
        // inclusive warp scan of c
        int s = c;
        #pragma unroll
        for (int d = 1; d < 32; d <<= 1) {
            int t = __shfl_up_sync(0xffffffffu, s, d);
            if (lane >= d) s += t;
        }
        int warpTotal = __shfl_sync(0xffffffffu, s, 31);
        int base = 0;
        if (lane == 31) base = atomicAdd(&g_total, warpTotal);
        base = __shfl_sync(0xffffffffu, base, 31);
        int off = base + s - c;   // exclusive within warp
        if (i < nR) { g_off[i] = off; g_cur[i] = off; }
    }
}

// ---------------- bin: place {li, f} into per-node segments ------------------
__global__ __launch_bounds__(256) void bin_kernel(
    const int* __restrict__ idxL, const int* __restrict__ idxR,
    const float* __restrict__ ef, int nE)
{
    int i = blockIdx.x * blockDim.x + threadIdx.x;
    int stride = gridDim.x * blockDim.x;
    for (int e = i; e < nE; e += stride) {
        int r = idxR[e];
        int li = idxL[e];
        float f = ef[e];
        int pos = atomicAdd(&g_cur[r], 1);
        g_sorted[pos] = make_int2(li, __float_as_int(f));
    }
}

// ---------------- fused projections: left and right in one launch ------------
__global__ __launch_bounds__(128) void proj_kernel(
    const float* __restrict__ XL, const float* __restrict__ WL, const float* __restrict__ bL,
    const float* __restrict__ XR, const float* __restrict__ WR,
    int nL, int nR, int nbL)
{
    bool isL = (int)blockIdx.x < nbL;
    const float* X = isL ? XL : XR;
    const float* W = isL ? WL : WR;
    float* Y = isL ? g_left_proj : g_right_proj;
    int n = isL ? nL : nR;
    int bid = isL ? blockIdx.x : blockIdx.x - nbL;

    __shared__ float WT[EMB * EMB];  // WT[k*64+j] = W[j*64+k]
    __shared__ float bsh[EMB];
    for (int i = threadIdx.x; i < EMB * EMB; i += blockDim.x) {
        int j = i >> 6, k = i & 63;
        WT[k * EMB + j] = W[i];
    }
    if (threadIdx.x < EMB) bsh[threadIdx.x] = isL ? bL[threadIdx.x] : 0.f;
    __syncthreads();

    int row = bid * blockDim.x + threadIdx.x;
    if (row >= n) return;
    float acc[EMB];
    #pragma unroll
    for (int j = 0; j < EMB; j++) acc[j] = bsh[j];
    const float4* Xr = (const float4*)(X + (size_t)row * EMB);
    #pragma unroll 2
    for (int k4 = 0; k4 < EMB / 4; k4++) {
        float4 xv = Xr[k4];
        const float* wp = &WT[(k4 * 4) * EMB];
        #pragma unroll
        for (int j = 0; j < EMB; j++) acc[j] = fmaf(wp[j], xv.x, acc[j]);
        #pragma unroll
        for (int j = 0; j < EMB; j++) acc[j] = fmaf(wp[EMB + j], xv.y, acc[j]);
        #pragma unroll
        for (int j = 0; j < EMB; j++) acc[j] = fmaf(wp[2 * EMB + j], xv.z, acc[j]);
        #pragma unroll
        for (int j = 0; j < EMB; j++) acc[j] = fmaf(wp[3 * EMB + j], xv.w, acc[j]);
    }
    float4* Yr = (float4*)(Y + (size_t)row * EMB);
    #pragma unroll
    for (int q = 0; q < EMB / 4; q++)
        Yr[q] = make_float4(acc[4 * q], acc[4 * q + 1], acc[4 * q + 2], acc[4 * q + 3]);
}

// ---------------- BN1 stats over sorted edges (gather, rp once/node) ---------
__global__ __launch_bounds__(256) void stats_kernel(
    const float* __restrict__ Wedge, int nR)
{
    int lane = threadIdx.x & 31;
    int hl = lane & 15;
    int grp = (blockIdx.x * blockDim.x + threadIdx.x) >> 4;
    int ngrp = (gridDim.x * blockDim.x) >> 4;
    float4 we = ((const float4*)Wedge)[hl];
    float4 s = make_float4(0.f, 0.f, 0.f, 0.f);
    float4 sq = make_float4(0.f, 0.f, 0.f, 0.f);
    const float4* LP = (const float4*)g_left_proj;
    const float4* RP = (const float4*)g_right_proj;

    for (int r = grp; r < nR; r += ngrp) {
        int cnt = g_cnt[r];
        int off = g_off[r];
        float4 rp = RP[(size_t)r * 16 + hl];
        float bx = rp.x, by = rp.y, bz = rp.z, bw = rp.w;
        int k = 0;
        for (; k + 1 < cnt; k += 2) {
            int2 a = g_sorted[off + k];
            int2 b = g_sorted[off + k + 1];
            float4 la = LP[(size_t)a.x * 16 + hl];
            float4 lb = LP[(size_t)b.x * 16 + hl];
            float fa = __int_as_float(a.y);
            float fb = __int_as_float(b.y);
            float x;
            x = fmaf(fa, we.x, la.x + bx); s.x += x; sq.x = fmaf(x, x, sq.x);
            x = fmaf(fa, we.y, la.y + by); s.y += x; sq.y = fmaf(x, x, sq.y);
            x = fmaf(fa, we.z, la.z + bz); s.z += x; sq.z = fmaf(x, x, sq.z);
            x = fmaf(fa, we.w, la.w + bw); s.w += x; sq.w = fmaf(x, x, sq.w);
            x = fmaf(fb, we.x, lb.x + bx); s.x += x; sq.x = fmaf(x, x, sq.x);
            x = fmaf(fb, we.y, lb.y + by); s.y += x; sq.y = fmaf(x, x, sq.y);
            x = fmaf(fb, we.z, lb.z + bz); s.z += x; sq.z = fmaf(x, x, sq.z);
            x = fmaf(fb, we.w, lb.w + bw); s.w += x; sq.w = fmaf(x, x, sq.w);
        }
        if (k < cnt) {
            int2 a = g_sorted[off + k];
            float4 la = LP[(size_t)a.x * 16 + hl];
            float fa = __int_as_float(a.y);
            float x;
            x = fmaf(fa, we.x, la.x + bx); s.x += x; sq.x = fmaf(x, x, sq.x);
            x = fmaf(fa, we.y, la.y + by); s.y += x; sq.y = fmaf(x, x, sq.y);
            x = fmaf(fa, we.z, la.z + bz); s.z += x; sq.z = fmaf(x, x, sq.z);
            x = fmaf(fa, we.w, la.w + bw); s.w += x; sq.w = fmaf(x, x, sq.w);
        }
    }
    // combine the two 16-lane halves (same columns), then block/global reduce
    s.x += __shfl_xor_sync(0xffffffffu, s.x, 16);
    s.y += __shfl_xor_sync(0xffffffffu, s.y, 16);
    s.z += __shfl_xor_sync(0xffffffffu, s.z, 16);
    s.w += __shfl_xor_sync(0xffffffffu, s.w, 16);
    sq.x += __shfl_xor_sync(0xffffffffu, sq.x, 16);
    sq.y += __shfl_xor_sync(0xffffffffu, sq.y, 16);
    sq.z += __shfl_xor_sync(0xffffffffu, sq.z, 16);
    sq.w += __shfl_xor_sync(0xffffffffu, sq.w, 16);

    __shared__ float cs[EMB], cq[EMB];
    if (threadIdx.x < EMB) { cs[threadIdx.x] = 0.f; cq[threadIdx.x] = 0.f; }
    __syncthreads();
    if (lane < 16) {
        atomicAdd(&cs[4 * hl + 0], s.x);
        atomicAdd(&cs[4 * hl + 1], s.y);
        atomicAdd(&cs[4 * hl + 2], s.z);
        atomicAdd(&cs[4 * hl + 3], s.w);
        atomicAdd(&cq[4 * hl + 0], sq.x);
        atomicAdd(&cq[4 * hl + 1], sq.y);
        atomicAdd(&cq[4 * hl + 2], sq.z);
        atomicAdd(&cq[4 * hl + 3], sq.w);
    }
    __syncthreads();
    if (threadIdx.x < EMB) {
        atomicAdd(&g_sum1[threadIdx.x], cs[threadIdx.x]);
        atomicAdd(&g_sumsq1[threadIdx.x], cq[threadIdx.x]);
    }
}

// ---------------- BN finalize ------------------------------------------------
__global__ void bn_fin_kernel(const float* __restrict__ sum, const float* __restrict__ sumsq,
                              const float* __restrict__ gamma, const float* __restrict__ beta,
                              float* __restrict__ scale, float* __restrict__ shift, float invN)
{
    int c = threadIdx.x;
    if (c < EMB) {
        float m = sum[c] * invN;
        float v = sumsq[c] * invN - m * m;
        float sc = gamma[c] * rsqrtf(v + BN_EPS);
        scale[c] = sc;
        shift[c] = beta[c] - m * sc;
    }
}

// ---------------- segment sum (gather; no atomics, writes S once) ------------
__global__ __launch_bounds__(256) void seg_kernel(const float* __restrict__ Wedge, int nR)
{
    int lane = threadIdx.x & 31;
    int hl = lane & 15;
    int grp = (blockIdx.x * blockDim.x + threadIdx.x) >> 4;
    int ngrp = (gridDim.x * blockDim.x) >> 4;
    float4 we = ((const float4*)Wedge)[hl];
    float4 sc = ((const float4*)g_scale1)[hl];
    float4 sh = ((const float4*)g_shift1)[hl];
    const float4* LP = (const float4*)g_left_proj;
    const float4* RP = (const float4*)g_right_proj;
    float4* Sv = (float4*)g_S;

    for (int r = grp; r < nR; r += ngrp) {
        int cnt = g_cnt[r];
        int off = g_off[r];
        float4 rp = RP[(size_t)r * 16 + hl];
        float bx = rp.x, by = rp.y, bz = rp.z, bw = rp.w;
        float4 acc = make_float4(0.f, 0.f, 0.f, 0.f);
        int k = 0;
        for (; k + 1 < cnt; k += 2) {
            int2 a = g_sorted[off + k];
            int2 b = g_sorted[off + k + 1];
            float4 la = LP[(size_t)a.x * 16 + hl];
            float4 lb = LP[(size_t)b.x * 16 + hl];
            float fa = __int_as_float(a.y);
            float fb = __int_as_float(b.y);
            float x;
            x = fmaf(fa, we.x, la.x + bx); acc.x += fmaxf(fmaf(x, sc.x, sh.x), 0.f);
            x = fmaf(fa, we.y, la.y + by); acc.y += fmaxf(fmaf(x, sc.y, sh.y), 0.f);
            x = fmaf(fa, we.z, la.z + bz); acc.z += fmaxf(fmaf(x, sc.z, sh.z), 0.f);
            x = fmaf(fa, we.w, la.w + bw); acc.w += fmaxf(fmaf(x, sc.w, sh.w), 0.f);
            x = fmaf(fb, we.x, lb.x + bx); acc.x += fmaxf(fmaf(x, sc.x, sh.x), 0.f);
            x = fmaf(fb, we.y, lb.y + by); acc.y += fmaxf(fmaf(x, sc.y, sh.y), 0.f);
            x = fmaf(fb, we.z, lb.z + bz); acc.z += fmaxf(fmaf(x, sc.z, sh.z), 0.f);
            x = fmaf(fb, we.w, lb.w + bw); acc.w += fmaxf(fmaf(x, sc.w, sh.w), 0.f);
        }
        if (k < cnt) {
            int2 a = g_sorted[off + k];
            float4 la = LP[(size_t)a.x * 16 + hl];
            float fa = __int_as_float(a.y);
            float x;
            x = fmaf(fa, we.x, la.x + bx); acc.x += fmaxf(fmaf(x, sc.x, sh.x), 0.f);
            x = fmaf(fa, we.y, la.y + by); acc.y += fmaxf(fmaf(x, sc.y, sh.y), 0.f);
            x = fmaf(fa, we.z, la.z + bz); acc.z += fmaxf(fmaf(x, sc.z, sh.z), 0.f);
            x = fmaf(fa, we.w, la.w + bw); acc.w += fmaxf(fmaf(x, sc.w, sh.w), 0.f);
        }
        Sv[(size_t)r * 16 + hl] = acc;
    }
}

// ---------------- conv = S @ Wf^T + cnt*b, fused BN2 column stats ------------
__global__ __launch_bounds__(128) void conv_stats_kernel(
    const float* __restrict__ X, const float* __restrict__ W,
    const float* __restrict__ bias, float* __restrict__ Y, int n)
{
    __shared__ float WT[EMB * EMB];
    __shared__ float bsh[EMB];
    __shared__ float cs[EMB], cq[EMB];
    for (int i = threadIdx.x; i < EMB * EMB; i += blockDim.x) {
        int j = i >> 6, k = i & 63;
        WT[k * EMB + j] = W[i];
    }
    if (threadIdx.x < EMB) {
        bsh[threadIdx.x] = bias[threadIdx.x];
        cs[threadIdx.x] = 0.f;
        cq[threadIdx.x] = 0.f;
    }
    __syncthreads();

    int row = blockIdx.x * blockDim.x + threadIdx.x;
    int lane = threadIdx.x & 31;
    bool valid = row < n;
    float acc[EMB];
    if (valid) {
        float bs = (float)g_cnt[row];
        #pragma unroll
        for (int j = 0; j < EMB; j++) acc[j] = bsh[j] * bs;
        const float4* Xr = (const float4*)(X + (size_t)row * EMB);
        #pragma unroll 2
        for (int k4 = 0; k4 < EMB / 4; k4++) {
            float4 xv = Xr[k4];
            const float* wp = &WT[(k4 * 4) * EMB];
            #pragma unroll
            for (int j = 0; j < EMB; j++) acc[j] = fmaf(wp[j], xv.x, acc[j]);
            #pragma unroll
            for (int j = 0; j < EMB; j++) acc[j] = fmaf(wp[EMB + j], xv.y, acc[j]);
            #pragma unroll
            for (int j = 0; j < EMB; j++) acc[j] = fmaf(wp[2 * EMB + j], xv.z, acc[j]);
            #pragma unroll
            for (int j = 0; j < EMB; j++) acc[j] = fmaf(wp[3 * EMB + j], xv.w, acc[j]);
        }
        float4* Yr = (float4*)(Y + (size_t)row * EMB);
        #pragma unroll
        for (int q = 0; q < EMB / 4; q++)
            Yr[q] = make_float4(acc[4 * q], acc[4 * q + 1], acc[4 * q + 2], acc[4 * q + 3]);
    } else {
        #pragma unroll
        for (int j = 0; j < EMB; j++) acc[j] = 0.f;
    }
    // per-warp column reduction into shared stats
    #pragma unroll
    for (int j = 0; j < EMB; j++) {
        float v = acc[j];
        float v2 = v * v;
        #pragma unroll
        for (int o = 16; o; o >>= 1) {
            v  += __shfl_xor_sync(0xffffffffu, v, o);
            v2 += __shfl_xor_sync(0xffffffffu, v2, o);
        }
        if (lane == 0) { atomicAdd(&cs[j], v); atomicAdd(&cq[j], v2); }
    }
    __syncthreads();
    if (threadIdx.x < EMB) {
        atomicAdd(&g_sum2[threadIdx.x], cs[threadIdx.x]);
        atomicAdd(&g_sumsq2[threadIdx.x], cq[threadIdx.x]);
    }
}

// ---------------- final: bn2 + concat + 2-layer MLP --------------------------
__global__ __launch_bounds__(128) void final_kernel(
    const float* __restrict__ right,
    const float* __restrict__ W1, const float* __restrict__ b1,
    const float* __restrict__ W2, const float* __restrict__ b2,
    float* __restrict__ out, int nR)
{
    __shared__ float Wsh[2 * EMB * EMB];
    __shared__ float sb[EMB], ssc[EMB], ssh[EMB];
    for (int i = threadIdx.x; i < 2 * EMB * EMB; i += blockDim.x) {
        int j = i >> 7, c = i & 127;       // W1 is [64,128]
        Wsh[c * EMB + j] = W1[i];
    }
    if (threadIdx.x < EMB) {
        sb[threadIdx.x] = b1[threadIdx.x];
        ssc[threadIdx.x] = g_scale2[threadIdx.x];
        ssh[threadIdx.x] = g_shift2[threadIdx.x];
    }
    __syncthreads();

    int row = blockIdx.x * blockDim.x + threadIdx.x;
    float h[EMB];
    if (row < nR) {
        #pragma unroll
        for (int j = 0; j < EMB; j++) h[j] = sb[j];
        const float4* cv = (const float4*)(g_conv + (size_t)row * EMB);
        #pragma unroll 2
        for (int k4 = 0; k4 < 16; k4++) {
            float4 v = cv[k4];
            int c = k4 * 4;
            float x0 = fmaf(v.x, ssc[c], ssh[c]);
            float x1 = fmaf(v.y, ssc[c + 1], ssh[c + 1]);
            float x2 = fmaf(v.z, ssc[c + 2], ssh[c + 2]);
            float x3 = fmaf(v.w, ssc[c + 3], ssh[c + 3]);
            const float* wp = &Wsh[c * EMB];
            #pragma unroll
            for (int j = 0; j < EMB; j++) h[j] = fmaf(wp[j], x0, h[j]);
            #pragma unroll
            for (int j = 0; j < EMB; j++) h[j] = fmaf(wp[EMB + j], x1, h[j]);
            #pragma unroll
            for (int j = 0; j < EMB; j++) h[j] = fmaf(wp[2 * EMB + j], x2, h[j]);
            #pragma unroll
            for (int j = 0; j < EMB; j++) h[j] = fmaf(wp[3 * EMB + j], x3, h[j]);
        }
        const float4* rf = (const float4*)(right + (size_t)row * EMB);
        #pragma unroll 2
        for (int k4 = 0; k4 < 16; k4++) {
            float4 v = rf[k4];
            int c = 64 + k4 * 4;
            const float* wp = &Wsh[c * EMB];
            #pragma unroll
            for (int j = 0; j < EMB; j++) h[j] = fmaf(wp[j], v.x, h[j]);
            #pragma unroll
            for (int j = 0; j < EMB; j++) h[j] = fmaf(wp[EMB + j], v.y, h[j]);
            #pragma unroll
            for (int j = 0; j < EMB; j++) h[j] = fmaf(wp[2 * EMB + j], v.z, h[j]);
            #pragma unroll
            for (int j = 0; j < EMB; j++) h[j] = fmaf(wp[3 * EMB + j], v.w, h[j]);
        }
        #pragma unroll
        for (int j = 0; j < EMB; j++) h[j] = fmaxf(h[j], 0.f);
    }
    __syncthreads();
    for (int i = threadIdx.x; i < EMB * EMB; i += blockDim.x) {
        int j = i >> 6, c = i & 63;
        Wsh[c * EMB + j] = W2[i];
    }
    if (threadIdx.x < EMB) sb[threadIdx.x] = b2[threadIdx.x];
    __syncthreads();
    if (row < nR) {
        float* orow = out + (size_t)row * EMB;
        #pragma unroll
        for (int jb = 0; jb < 4; jb++) {
            float acc[16];
            #pragma unroll
            for (int j = 0; j < 16; j++) acc[j] = sb[jb * 16 + j];
            #pragma unroll 4
            for (int c = 0; c < EMB; c++) {
                float hc = h[c];
                const float* wp = &Wsh[c * EMB + jb * 16];
                #pragma unroll
                for (int j = 0; j < 16; j++) acc[j] = fmaf(wp[j], hc, acc[j]);
            }
            float4* o4 = (float4*)(orow + jb * 16);
            #pragma unroll
            for (int q = 0; q < 4; q++)
                o4[q] = make_float4(fmaxf(acc[4 * q], 0.f), fmaxf(acc[4 * q + 1], 0.f),
                                    fmaxf(acc[4 * q + 2], 0.f), fmaxf(acc[4 * q + 3], 0.f));
        }
    }
}

// ---------------- launch -----------------------------------------------------
extern "C" void kernel_launch(void* const* d_in, const int* in_sizes, int n_in,
                              void* d_out, int out_size)
{
    const float* left  = (const float*)d_in[0];
    const int*   eidx  = (const int*)d_in[1];
    const float* ef    = (const float*)d_in[2];
    const float* right = (const float*)d_in[3];
    int off = (n_in >= 19) ? 1 : 0;   // skip output_size scalar input if present
    const float* W_left    = (const float*)d_in[4 + off];
    const float* b_left    = (const float*)d_in[5 + off];
    const float* W_edge    = (const float*)d_in[6 + off];
    const float* W_right   = (const float*)d_in[7 + off];
    const float* bn1_gamma = (const float*)d_in[8 + off];
    const float* bn1_beta  = (const float*)d_in[9 + off];
    const float* W_final   = (const float*)d_in[10 + off];
    const float* b_final   = (const float*)d_in[11 + off];
    const float* bn2_gamma = (const float*)d_in[12 + off];
    const float* bn2_beta  = (const float*)d_in[13 + off];
    const float* W_out1    = (const float*)d_in[14 + off];
    const float* b_out1    = (const float*)d_in[15 + off];
    const float* W_out2    = (const float*)d_in[16 + off];
    const float* b_out2    = (const float*)d_in[17 + off];
    float* out = (float*)d_out;

    int nL = in_sizes[0] / EMB;
    int nE = in_sizes[2];
    int nR = in_sizes[3] / EMB;

    float* Sp; cudaGetSymbolAddress((void**)&Sp, g_S);
    float* cp; cudaGetSymbolAddress((void**)&cp, g_conv);
    float* s1; cudaGetSymbolAddress((void**)&s1, g_sum1);
    float* q1; cudaGetSymbolAddress((void**)&q1, g_sumsq1);
    float* sc1; cudaGetSymbolAddress((void**)&sc1, g_scale1);
    float* sh1; cudaGetSymbolAddress((void**)&sh1, g_shift1);
    float* s2; cudaGetSymbolAddress((void**)&s2, g_sum2);
    float* q2; cudaGetSymbolAddress((void**)&q2, g_sumsq2);
    float* sc2; cudaGetSymbolAddress((void**)&sc2, g_scale2);
    float* sh2; cudaGetSymbolAddress((void**)&sh2, g_shift2);

    int nbL = (nL + 127) / 128;
    int nbR = (nR + 127) / 128;

    // 0) zero counters/stats
    zero_kernel<<<(nR + 255) / 256, 256>>>(nR);
    // 1) degree histogram
    count_kernel<<<1184, 256>>>(eidx + nE, nE);
    // 2) contiguous segment offsets (order-free, warp-aggregated)
    assign_kernel<<<(nR + 255) / 256, 256>>>(nR);
    // 3) bin {left_idx, f} into segments
    bin_kernel<<<1184, 256>>>(eidx, eidx + nE, ef, nE);
    // 4) projections
    proj_kernel<<<nbL + nbR, 128>>>(left, W_left, b_left, right, W_right, nL, nR, nbL);
    // 5) BN1 stats over sorted edges (gather)
    stats_kernel<<<1184, 256>>>(W_edge, nR);
    bn_fin_kernel<<<1, EMB>>>(s1, q1, bn1_gamma, bn1_beta, sc1, sh1, 1.0f / (float)nE);
    // 6) segment sum (gather, no atomics)
    seg_kernel<<<1184, 256>>>(W_edge, nR);
    // 7) conv = S @ W_final^T + cnt * b_final, fused BN2 stats
    conv_stats_kernel<<<nbR, 128>>>(Sp, W_final, b_final, cp, nR);
    bn_fin_kernel<<<1, EMB>>>(s2, q2, bn2_gamma, bn2_beta, sc2, sh2, 1.0f / (float)nR);
    // 8) final MLP
    final_kernel<<<nbR, 128>>>(right, W_out1, b_out1, W_out2, b_out2, out, nR);
}